// round 5
// baseline (speedup 1.0000x reference)
#include <cuda_runtime.h>
#include <cstdint>

#define BB 16
#define CC 512
#define HWD 1024

// Scratch (device globals)
__device__ float g_xT[(size_t)HWD * (BB * CC)];   // 32MB  xT[o][m], ld=8192
__device__ float g_e [(size_t)BB * HWD * HWD];    // 64MB  e[b][o][h] (softmax in place)
__device__ float g_n2T[(size_t)BB * HWD * CC];    // 32MB  n2T[b][h][c]
__device__ float g_aT [(size_t)BB * HWD * HWD];   // 64MB  aT[b][j][k]

// ---------------------------------------------------------------------------
#define GM_BM 128
#define GM_BN 128
#define GM_BK 16
#define GM_STAGES 3
#define GM_LDS 20                                  // smem row stride (floats)
#define GM_TILE_B (128 * GM_LDS * 4)               // 10240 B per tile
#define GM_STAGE_B (2 * GM_TILE_B)                 // A + B
#define GM_SMEM (GM_STAGES * GM_STAGE_B)           // 61440 B

__device__ __forceinline__ uint32_t smem_u32(const void* p) {
    uint32_t a;
    asm("{ .reg .u64 t; cvta.to.shared.u64 t, %1; cvt.u32.u64 %0, t; }" : "=r"(a) : "l"(p));
    return a;
}
__device__ __forceinline__ uint32_t cvt_tf32(float v) {
    uint32_t r;
    asm("cvt.rna.tf32.f32 %0, %1;" : "=r"(r) : "f"(v));
    return r;
}
__device__ __forceinline__ void cp16(uint32_t saddr, const float* g) {
    asm volatile("cp.async.ca.shared.global [%0], [%1], 16;" :: "r"(saddr), "l"(g));
}
__device__ __forceinline__ void cp_commit() {
    asm volatile("cp.async.commit_group;");
}
template <int N>
__device__ __forceinline__ void cp_wait() {
    asm volatile("cp.async.wait_group %0;" :: "n"(N));
}
__device__ __forceinline__ void mma8(float* d, const uint32_t* a, const uint32_t* b) {
    asm volatile(
        "mma.sync.aligned.m16n8k8.row.col.f32.tf32.tf32.f32 "
        "{%0,%1,%2,%3}, {%4,%5,%6,%7}, {%8,%9}, {%0,%1,%2,%3};"
        : "+f"(d[0]), "+f"(d[1]), "+f"(d[2]), "+f"(d[3])
        : "r"(a[0]), "r"(a[1]), "r"(a[2]), "r"(a[3]), "r"(b[0]), "r"(b[1]));
}

// ---------------------------------------------------------------------------
// C[m][n] = sum_k A[m][k] * B[n][k]  (both operands K-major).
// PASSES = 3: tf32x3 (fp32-class accuracy).  PASSES = 1: plain tf32.
// ---------------------------------------------------------------------------
template <int PASSES>
__global__ __launch_bounds__(256, 1) void gemm_tf32(
    const float* __restrict__ A, const float* __restrict__ B, float* __restrict__ C,
    int K, int lda, int ldb, int ldc, size_t sA, size_t sB, size_t sC)
{
    extern __shared__ float smem[];
    const uint32_t sbase = smem_u32(smem);

    const int tid = threadIdx.x;
    const int wid = tid >> 5;
    const int lane = tid & 31;
    const int warp_m = (wid & 1) * 64;   // 2 warps over M
    const int warp_n = (wid >> 1) * 32;  // 4 warps over N

    A += (size_t)blockIdx.z * sA;
    B += (size_t)blockIdx.z * sB;
    C += (size_t)blockIdx.z * sC;
    const int bm = blockIdx.y * GM_BM;
    const int bn = blockIdx.x * GM_BN;

    // global/shared coords for cp.async: 2 chunks of 16B each for A and B
    const int r0 = tid >> 2;            // rows 0..63 (p=0), 64..127 (p=1)
    const int q0 = (tid & 3) * 4;       // k offset within BK=16
    const float* Ag = A + (size_t)(bm + r0) * lda + q0;
    const float* Bg = B + (size_t)(bn + r0) * ldb + q0;

    const int nk = K / GM_BK;

    auto load_stage = [&](int kt, int s) {
        const uint32_t sa = sbase + s * GM_STAGE_B;
        const uint32_t sb = sa + GM_TILE_B;
        #pragma unroll
        for (int p = 0; p < 2; p++) {
            const int row = r0 + p * 64;
            cp16(sa + (row * GM_LDS + q0) * 4, Ag + (size_t)(p * 64) * lda + kt * GM_BK);
            cp16(sb + (row * GM_LDS + q0) * 4, Bg + (size_t)(p * 64) * ldb + kt * GM_BK);
        }
        cp_commit();
    };

    // prefetch STAGES-1 tiles
    load_stage(0, 0);
    load_stage(1, 1);

    float acc[4][4][4];
    #pragma unroll
    for (int i = 0; i < 4; i++)
        #pragma unroll
        for (int j = 0; j < 4; j++)
            #pragma unroll
            for (int t = 0; t < 4; t++)
                acc[i][j][t] = 0.0f;

    const int fr = lane >> 2;   // fragment row / n index
    const int fc = lane & 3;    // fragment k index

    for (int kt = 0; kt < nk; kt++) {
        cp_wait<GM_STAGES - 2>();
        __syncthreads();

        if (kt + 2 < nk) load_stage(kt + 2, (kt + 2) % GM_STAGES);

        const int s = kt % GM_STAGES;
        const float* As = smem + (size_t)s * GM_STAGE_B / 4;
        const float* Bs = As + GM_TILE_B / 4;

        #pragma unroll
        for (int k8 = 0; k8 < 2; k8++) {
            const int kb = k8 * 8;
            uint32_t Ah[4][4], Al[4][4], Bh[4][2], Bl[4][2];
            #pragma unroll
            for (int i = 0; i < 4; i++) {
                const int rr = warp_m + i * 16 + fr;
                #pragma unroll
                for (int t = 0; t < 4; t++) {
                    float v = As[(rr + (t & 1) * 8) * GM_LDS + kb + fc + (t >> 1) * 4];
                    Ah[i][t] = cvt_tf32(v);
                    if (PASSES == 3)
                        Al[i][t] = cvt_tf32(v - __uint_as_float(Ah[i][t]));
                }
            }
            #pragma unroll
            for (int j = 0; j < 4; j++) {
                const int nn = warp_n + j * 8 + fr;
                #pragma unroll
                for (int t = 0; t < 2; t++) {
                    float v = Bs[nn * GM_LDS + kb + fc + t * 4];
                    Bh[j][t] = cvt_tf32(v);
                    if (PASSES == 3)
                        Bl[j][t] = cvt_tf32(v - __uint_as_float(Bh[j][t]));
                }
            }
            // pass hi*hi
            #pragma unroll
            for (int i = 0; i < 4; i++)
                #pragma unroll
                for (int j = 0; j < 4; j++)
                    mma8(acc[i][j], Ah[i], Bh[j]);
            if (PASSES == 3) {
                #pragma unroll
                for (int i = 0; i < 4; i++)
                    #pragma unroll
                    for (int j = 0; j < 4; j++)
                        mma8(acc[i][j], Ah[i], Bl[j]);
                #pragma unroll
                for (int i = 0; i < 4; i++)
                    #pragma unroll
                    for (int j = 0; j < 4; j++)
                        mma8(acc[i][j], Al[i], Bh[j]);
            }
        }
        __syncthreads();
    }

    // epilogue
    #pragma unroll
    for (int i = 0; i < 4; i++) {
        const int row0 = bm + warp_m + i * 16 + fr;
        #pragma unroll
        for (int j = 0; j < 4; j++) {
            const int col = bn + warp_n + j * 8 + fc * 2;
            *(float2*)&C[(size_t)row0 * ldc + col] = make_float2(acc[i][j][0], acc[i][j][1]);
            *(float2*)&C[(size_t)(row0 + 8) * ldc + col] = make_float2(acc[i][j][2], acc[i][j][3]);
        }
    }
}

// ---------------------------------------------------------------------------
// Tiled transpose: in[z][R][Cc] -> out[z][Cc][R]
// ---------------------------------------------------------------------------
__global__ __launch_bounds__(256) void transpose_k(
    const float* __restrict__ in, float* __restrict__ out, int R, int Cc)
{
    __shared__ float t[32][33];
    const int bx = blockIdx.x * 32;
    const int by = blockIdx.y * 32;
    const float* ib = in + (size_t)blockIdx.z * R * Cc;
    float* ob = out + (size_t)blockIdx.z * R * Cc;
    const int x = threadIdx.x, y = threadIdx.y;  // 32 x 8
    #pragma unroll
    for (int i = 0; i < 32; i += 8)
        t[y + i][x] = ib[(size_t)(by + y + i) * Cc + bx + x];
    __syncthreads();
    #pragma unroll
    for (int i = 0; i < 32; i += 8)
        ob[(size_t)(bx + y + i) * R + by + x] = t[x][y + i];
}

// ---------------------------------------------------------------------------
// In-place row softmax, row length 1024
// ---------------------------------------------------------------------------
__global__ __launch_bounds__(256) void softmax1024(float* __restrict__ e)
{
    const size_t row = blockIdx.x;
    float* p = e + row * (size_t)HWD;
    const int t = threadIdx.x;

    float v[4];
    float mx = -1e30f;
    #pragma unroll
    for (int i = 0; i < 4; i++) {
        v[i] = p[t + 256 * i];
        mx = fmaxf(mx, v[i]);
    }
    __shared__ float redm[8];
    __shared__ float reds[8];
    #pragma unroll
    for (int o = 16; o > 0; o >>= 1)
        mx = fmaxf(mx, __shfl_xor_sync(0xFFFFFFFFu, mx, o));
    if ((t & 31) == 0) redm[t >> 5] = mx;
    __syncthreads();
    float m = redm[0];
    #pragma unroll
    for (int i = 1; i < 8; i++) m = fmaxf(m, redm[i]);

    float sacc = 0.0f;
    #pragma unroll
    for (int i = 0; i < 4; i++) {
        v[i] = __expf(v[i] - m);
        sacc += v[i];
    }
    #pragma unroll
    for (int o = 16; o > 0; o >>= 1)
        sacc += __shfl_xor_sync(0xFFFFFFFFu, sacc, o);
    if ((t & 31) == 0) reds[t >> 5] = sacc;
    __syncthreads();
    float sum = reds[0];
    #pragma unroll
    for (int i = 1; i < 8; i++) sum += reds[i];

    const float inv = 1.0f / sum;
    #pragma unroll
    for (int i = 0; i < 4; i++)
        p[t + 256 * i] = v[i] * inv;
}

// ---------------------------------------------------------------------------
extern "C" void kernel_launch(void* const* d_in, const int* in_sizes, int n_in,
                              void* d_out, int out_size)
{
    const float* node1 = (const float*)d_in[0];  // [B, C, HW]
    const float* node2 = (const float*)d_in[1];  // [B, C, HW]
    const float* Wc    = (const float*)d_in[2];  // [HW, HW]
    float* out = (float*)d_out;                  // [B, C, HW]

    float *xT, *e, *n2T, *aT;
    cudaGetSymbolAddress((void**)&xT,  g_xT);
    cudaGetSymbolAddress((void**)&e,   g_e);
    cudaGetSymbolAddress((void**)&n2T, g_n2T);
    cudaGetSymbolAddress((void**)&aT,  g_aT);

    cudaFuncSetAttribute(gemm_tf32<3>,
                         cudaFuncAttributeMaxDynamicSharedMemorySize, GM_SMEM);
    cudaFuncSetAttribute(gemm_tf32<1>,
                         cudaFuncAttributeMaxDynamicSharedMemorySize, GM_SMEM);

    // GEMM1: xT[o][m] = sum_h Wc[o][h] * n1[m][h];  M=1024, N=8192, K=1024
    gemm_tf32<3><<<dim3(8192 / GM_BN, HWD / GM_BM, 1), 256, GM_SMEM>>>(
        Wc, node1, xT, HWD, HWD, HWD, 8192, 0, 0, 0);

    // n2T[b][h][c] = n2[b][c][h]
    transpose_k<<<dim3(HWD / 32, CC / 32, BB), dim3(32, 8)>>>(node2, n2T, CC, HWD);

    // GEMM2: e[b][o][h] = sum_c xT[o][b*512+c] * n2T[b][h][c];  M=1024, N=1024, K=512
    gemm_tf32<3><<<dim3(HWD / GM_BN, HWD / GM_BM, BB), 256, GM_SMEM>>>(
        xT, n2T, e, CC, 8192, CC, HWD,
        (size_t)CC, (size_t)HWD * CC, (size_t)HWD * HWD);

    // softmax over h, in place
    softmax1024<<<BB * HWD, 256>>>(e);

    // aT[b][j][k] = a[b][k][j]
    transpose_k<<<dim3(HWD / 32, HWD / 32, BB), dim3(32, 8)>>>(e, aT, HWD, HWD);

    // GEMM3: out[b][c][j] = sum_k n2[b][c][k] * aT[b][j][k];  M=512, N=1024, K=1024
    gemm_tf32<1><<<dim3(HWD / GM_BN, CC / GM_BM, BB), 256, GM_SMEM>>>(
        node2, aT, out, HWD, HWD, HWD, HWD,
        (size_t)CC * HWD, (size_t)HWD * HWD, (size_t)CC * HWD);
}

// round 6
// speedup vs baseline: 1.3023x; 1.3023x over previous
#include <cuda_runtime.h>
#include <cuda_fp16.h>
#include <cstdint>

#define BB 16
#define CC 512
#define HWD 1024

// Scratch (device globals)
__device__ float g_xT[(size_t)HWD * (BB * CC)];   // 32MB  xT[o][m], ld=8192
__device__ float g_e [(size_t)BB * HWD * HWD];    // 64MB  e[b][o][h] (softmax in place)
__device__ float g_n2T[(size_t)BB * HWD * CC];    // 32MB  n2T[b][h][c]
__device__ float g_aT [(size_t)BB * HWD * HWD];   // 64MB  aT[b][j][k]

// ---------------------------------------------------------------------------
// fp16 3-split GEMM:  C[m][n] = sum_k A[m][k] * B[n][k]  (both K-major)
// BM=BN=128, BK=32, 256 threads, 8 warps (2m x 4n), m16n8k16 HMMA.
// PASSES=3: h*h + h*m + m*h  (~tf32x3 / near-fp32 accuracy)
// PASSES=1: h*h only          (~tf32 single-pass accuracy)
// smem holds pre-split packed half2 tiles: AH, AM, BH, BM (u32 each).
// ---------------------------------------------------------------------------
#define FG_LDS 20                            // u32 per 128-row tile row
#define FG_TILE_U32 (128 * FG_LDS)           // 2560
#define FG_STAGE_U32 (4 * FG_TILE_U32)       // 10240 (AH,AM,BH,BM)
#define FG_SMEM_B (2 * FG_STAGE_U32 * 4)     // 81920 bytes, 2 stages

__device__ __forceinline__ uint32_t pack_h2(float x, float y) {
    __half2 h = __float22half2_rn(make_float2(x, y));
    return *reinterpret_cast<uint32_t*>(&h);
}
__device__ __forceinline__ float2 unpack_h2(uint32_t u) {
    __half2 h = *reinterpret_cast<__half2*>(&u);
    return __half22float2(h);
}
__device__ __forceinline__ void mma16(float* d, const uint32_t* a, const uint32_t* b) {
    asm volatile(
        "mma.sync.aligned.m16n8k16.row.col.f32.f16.f16.f32 "
        "{%0,%1,%2,%3}, {%4,%5,%6,%7}, {%8,%9}, {%0,%1,%2,%3};"
        : "+f"(d[0]), "+f"(d[1]), "+f"(d[2]), "+f"(d[3])
        : "r"(a[0]), "r"(a[1]), "r"(a[2]), "r"(a[3]), "r"(b[0]), "r"(b[1]));
}

template <int PASSES>
__global__ __launch_bounds__(256, 1) void gemm_f16s(
    const float* __restrict__ A, const float* __restrict__ B, float* __restrict__ C,
    int K, int lda, int ldb, int ldc, size_t sA, size_t sB, size_t sC,
    float a_scale, float c_scale)
{
    extern __shared__ uint32_t sm[];

    const int tid = threadIdx.x;
    const int wid = tid >> 5;
    const int lane = tid & 31;
    const int warp_m = (wid & 1) * 64;
    const int warp_n = (wid >> 1) * 32;

    A += (size_t)blockIdx.z * sA;
    B += (size_t)blockIdx.z * sB;
    C += (size_t)blockIdx.z * sC;
    const int bm = blockIdx.y * 128;
    const int bn = blockIdx.x * 128;

    // loader coords: 2 threads per tile row; each covers 16 consecutive k
    const int lrow = tid >> 1;
    const int lkh = (tid & 1) * 16;
    const float* Ag = A + (size_t)(bm + lrow) * lda + lkh;
    const float* Bg = B + (size_t)(bn + lrow) * ldb + lkh;

    float4 ra[4], rb[4];   // register staging for next tile

    const int nk = K / 32;

    // ---- prologue: load kt=0 ----
    #pragma unroll
    for (int q = 0; q < 4; q++) {
        ra[q] = *(const float4*)(Ag + 4 * q);
        rb[q] = *(const float4*)(Bg + 4 * q);
    }

    float acc[4][4][4];
    #pragma unroll
    for (int i = 0; i < 4; i++)
        #pragma unroll
        for (int j = 0; j < 4; j++)
            #pragma unroll
            for (int t = 0; t < 4; t++)
                acc[i][j][t] = 0.0f;

    const int fr = lane >> 2;
    const int fc = lane & 3;
    const int sbase = lrow * FG_LDS + (lkh >> 1);

    // split + store current registers into stage st
    auto sts_stage = [&](int st) {
        uint32_t* AH = sm + st * FG_STAGE_U32;
        uint32_t* AM = AH + FG_TILE_U32;
        uint32_t* BH = AM + FG_TILE_U32;
        uint32_t* BM = BH + FG_TILE_U32;
        #pragma unroll
        for (int q = 0; q < 4; q++) {
            float ax = ra[q].x * a_scale, ay = ra[q].y * a_scale;
            float az = ra[q].z * a_scale, aw = ra[q].w * a_scale;
            uint32_t h01 = pack_h2(ax, ay);
            uint32_t h23 = pack_h2(az, aw);
            float2 f01 = unpack_h2(h01), f23 = unpack_h2(h23);
            uint32_t m01 = pack_h2(ax - f01.x, ay - f01.y);
            uint32_t m23 = pack_h2(az - f23.x, aw - f23.y);
            *(uint2*)&AH[sbase + 2 * q] = make_uint2(h01, h23);
            *(uint2*)&AM[sbase + 2 * q] = make_uint2(m01, m23);

            uint32_t bh01 = pack_h2(rb[q].x, rb[q].y);
            uint32_t bh23 = pack_h2(rb[q].z, rb[q].w);
            float2 g01 = unpack_h2(bh01), g23 = unpack_h2(bh23);
            uint32_t bm01 = pack_h2(rb[q].x - g01.x, rb[q].y - g01.y);
            uint32_t bm23 = pack_h2(rb[q].z - g23.x, rb[q].w - g23.y);
            *(uint2*)&BH[sbase + 2 * q] = make_uint2(bh01, bh23);
            *(uint2*)&BM[sbase + 2 * q] = make_uint2(bm01, bm23);
        }
    };

    sts_stage(0);
    __syncthreads();

    for (int kt = 0; kt < nk; kt++) {
        // prefetch next tile into registers
        if (kt + 1 < nk) {
            const float* a = Ag + (size_t)(kt + 1) * 32;
            const float* b = Bg + (size_t)(kt + 1) * 32;
            #pragma unroll
            for (int q = 0; q < 4; q++) {
                ra[q] = *(const float4*)(a + 4 * q);
                rb[q] = *(const float4*)(b + 4 * q);
            }
        }

        // ---- MMA on stage kt&1 ----
        {
            const int st = kt & 1;
            const uint32_t* AH = sm + st * FG_STAGE_U32;
            const uint32_t* AM = AH + FG_TILE_U32;
            const uint32_t* BH = AM + FG_TILE_U32;
            const uint32_t* BM = BH + FG_TILE_U32;

            #pragma unroll
            for (int kk = 0; kk < 2; kk++) {
                const int kb = kk * 8 + fc;
                uint32_t Bh[4][2], Bm[4][2];
                #pragma unroll
                for (int j = 0; j < 4; j++) {
                    const int nb = (warp_n + j * 8 + fr) * FG_LDS;
                    Bh[j][0] = BH[nb + kb];
                    Bh[j][1] = BH[nb + kb + 4];
                    if (PASSES == 3) {
                        Bm[j][0] = BM[nb + kb];
                        Bm[j][1] = BM[nb + kb + 4];
                    }
                }
                #pragma unroll
                for (int i = 0; i < 4; i++) {
                    const int r0 = (warp_m + i * 16 + fr) * FG_LDS;
                    const int r8 = r0 + 8 * FG_LDS;
                    uint32_t Ah[4] = {AH[r0 + kb], AH[r8 + kb],
                                      AH[r0 + kb + 4], AH[r8 + kb + 4]};
                    uint32_t Am[4];
                    if (PASSES == 3) {
                        Am[0] = AM[r0 + kb];     Am[1] = AM[r8 + kb];
                        Am[2] = AM[r0 + kb + 4]; Am[3] = AM[r8 + kb + 4];
                    }
                    #pragma unroll
                    for (int j = 0; j < 4; j++) {
                        mma16(acc[i][j], Ah, Bh[j]);
                        if (PASSES == 3) {
                            mma16(acc[i][j], Ah, Bm[j]);
                            mma16(acc[i][j], Am, Bh[j]);
                        }
                    }
                }
            }
        }

        // split + store prefetched tile into the other stage
        if (kt + 1 < nk) sts_stage((kt + 1) & 1);
        __syncthreads();
    }

    // epilogue
    #pragma unroll
    for (int i = 0; i < 4; i++) {
        const int row0 = bm + warp_m + i * 16 + fr;
        #pragma unroll
        for (int j = 0; j < 4; j++) {
            const int col = bn + warp_n + j * 8 + fc * 2;
            *(float2*)&C[(size_t)row0 * ldc + col] =
                make_float2(acc[i][j][0] * c_scale, acc[i][j][1] * c_scale);
            *(float2*)&C[(size_t)(row0 + 8) * ldc + col] =
                make_float2(acc[i][j][2] * c_scale, acc[i][j][3] * c_scale);
        }
    }
}

// ---------------------------------------------------------------------------
// Tiled transpose: in[z][R][Cc] -> out[z][Cc][R]
// ---------------------------------------------------------------------------
__global__ __launch_bounds__(256) void transpose_k(
    const float* __restrict__ in, float* __restrict__ out, int R, int Cc)
{
    __shared__ float t[32][33];
    const int bx = blockIdx.x * 32;
    const int by = blockIdx.y * 32;
    const float* ib = in + (size_t)blockIdx.z * R * Cc;
    float* ob = out + (size_t)blockIdx.z * R * Cc;
    const int x = threadIdx.x, y = threadIdx.y;  // 32 x 8
    #pragma unroll
    for (int i = 0; i < 32; i += 8)
        t[y + i][x] = ib[(size_t)(by + y + i) * Cc + bx + x];
    __syncthreads();
    #pragma unroll
    for (int i = 0; i < 32; i += 8)
        ob[(size_t)(bx + y + i) * R + by + x] = t[x][y + i];
}

// ---------------------------------------------------------------------------
// In-place row softmax, row length 1024
// ---------------------------------------------------------------------------
__global__ __launch_bounds__(256) void softmax1024(float* __restrict__ e)
{
    const size_t row = blockIdx.x;
    float* p = e + row * (size_t)HWD;
    const int t = threadIdx.x;

    float v[4];
    float mx = -1e30f;
    #pragma unroll
    for (int i = 0; i < 4; i++) {
        v[i] = p[t + 256 * i];
        mx = fmaxf(mx, v[i]);
    }
    __shared__ float redm[8];
    __shared__ float reds[8];
    #pragma unroll
    for (int o = 16; o > 0; o >>= 1)
        mx = fmaxf(mx, __shfl_xor_sync(0xFFFFFFFFu, mx, o));
    if ((t & 31) == 0) redm[t >> 5] = mx;
    __syncthreads();
    float m = redm[0];
    #pragma unroll
    for (int i = 1; i < 8; i++) m = fmaxf(m, redm[i]);

    float sacc = 0.0f;
    #pragma unroll
    for (int i = 0; i < 4; i++) {
        v[i] = __expf(v[i] - m);
        sacc += v[i];
    }
    #pragma unroll
    for (int o = 16; o > 0; o >>= 1)
        sacc += __shfl_xor_sync(0xFFFFFFFFu, sacc, o);
    if ((t & 31) == 0) reds[t >> 5] = sacc;
    __syncthreads();
    float sum = reds[0];
    #pragma unroll
    for (int i = 1; i < 8; i++) sum += reds[i];

    const float inv = 1.0f / sum;
    #pragma unroll
    for (int i = 0; i < 4; i++)
        p[t + 256 * i] = v[i] * inv;
}

// ---------------------------------------------------------------------------
extern "C" void kernel_launch(void* const* d_in, const int* in_sizes, int n_in,
                              void* d_out, int out_size)
{
    const float* node1 = (const float*)d_in[0];  // [B, C, HW]
    const float* node2 = (const float*)d_in[1];  // [B, C, HW]
    const float* Wc    = (const float*)d_in[2];  // [HW, HW]
    float* out = (float*)d_out;                  // [B, C, HW]

    float *xT, *e, *n2T, *aT;
    cudaGetSymbolAddress((void**)&xT,  g_xT);
    cudaGetSymbolAddress((void**)&e,   g_e);
    cudaGetSymbolAddress((void**)&n2T, g_n2T);
    cudaGetSymbolAddress((void**)&aT,  g_aT);

    cudaFuncSetAttribute(gemm_f16s<3>,
                         cudaFuncAttributeMaxDynamicSharedMemorySize, FG_SMEM_B);
    cudaFuncSetAttribute(gemm_f16s<1>,
                         cudaFuncAttributeMaxDynamicSharedMemorySize, FG_SMEM_B);

    // GEMM1: xT[o][m] = sum_h Wc[o][h] * n1[m][h];  M=1024, N=8192, K=1024
    // Wc prescaled by 2^10 in the loader (fp16 subnormal guard), epilogue * 2^-10.
    gemm_f16s<3><<<dim3(8192 / 128, HWD / 128, 1), 256, FG_SMEM_B>>>(
        Wc, node1, xT, HWD, HWD, HWD, 8192, 0, 0, 0,
        1024.0f, 1.0f / 1024.0f);

    // n2T[b][h][c] = n2[b][c][h]
    transpose_k<<<dim3(HWD / 32, CC / 32, BB), dim3(32, 8)>>>(node2, n2T, CC, HWD);

    // GEMM2: e[b][o][h] = sum_c xT[o][b*512+c] * n2T[b][h][c];  M=1024, N=1024, K=512
    gemm_f16s<3><<<dim3(HWD / 128, HWD / 128, BB), 256, FG_SMEM_B>>>(
        xT, n2T, e, CC, 8192, CC, HWD,
        (size_t)CC, (size_t)HWD * CC, (size_t)HWD * HWD,
        1.0f, 1.0f);

    // softmax over h, in place
    softmax1024<<<BB * HWD, 256>>>(e);

    // aT[b][j][k] = a[b][k][j]
    transpose_k<<<dim3(HWD / 32, HWD / 32, BB), dim3(32, 8)>>>(e, aT, HWD, HWD);

    // GEMM3: out[b][c][j] = sum_k n2[b][c][k] * aT[b][j][k];  M=512, N=1024, K=1024
    gemm_f16s<1><<<dim3(HWD / 128, CC / 128, BB), 256, FG_SMEM_B>>>(
        node2, aT, out, HWD, HWD, HWD, HWD,
        (size_t)CC * HWD, (size_t)HWD * HWD, (size_t)CC * HWD,
        1.0f, 1.0f);
}

// round 7
// speedup vs baseline: 1.4882x; 1.1428x over previous
#include <cuda_runtime.h>
#include <cuda_fp16.h>
#include <cstdint>

#define BB 16
#define CC 512
#define HWD 1024

// Pre-split half planes (device globals)
__device__ __half g_Wh [(size_t)HWD * HWD];
__device__ __half g_Wm [(size_t)HWD * HWD];
__device__ __half g_n1h[(size_t)BB * CC * HWD];
__device__ __half g_n1m[(size_t)BB * CC * HWD];
__device__ __half g_n2h[(size_t)BB * CC * HWD];
__device__ __half g_n2Th[(size_t)BB * HWD * CC];
__device__ __half g_n2Tm[(size_t)BB * HWD * CC];
__device__ __half g_xTh[(size_t)HWD * BB * CC];
__device__ __half g_xTm[(size_t)HWD * BB * CC];
__device__ __half g_aTh[(size_t)BB * HWD * HWD];
__device__ float  g_e  [(size_t)BB * HWD * HWD];

// ---------------------------------------------------------------------------
__device__ __forceinline__ uint32_t smem_u32(const void* p) {
    uint32_t a;
    asm("{ .reg .u64 t; cvta.to.shared.u64 t, %1; cvt.u32.u64 %0, t; }" : "=r"(a) : "l"(p));
    return a;
}
__device__ __forceinline__ void cp16(uint32_t saddr, const void* g) {
    asm volatile("cp.async.ca.shared.global [%0], [%1], 16;" :: "r"(saddr), "l"(g));
}
__device__ __forceinline__ void cp_commit() {
    asm volatile("cp.async.commit_group;");
}
template <int N>
__device__ __forceinline__ void cp_wait() {
    asm volatile("cp.async.wait_group %0;" :: "n"(N));
}
__device__ __forceinline__ void ldm4(uint32_t* r, uint32_t addr) {
    asm volatile("ldmatrix.sync.aligned.m8n8.x4.shared.b16 {%0,%1,%2,%3}, [%4];"
                 : "=r"(r[0]), "=r"(r[1]), "=r"(r[2]), "=r"(r[3]) : "r"(addr));
}
__device__ __forceinline__ void mma16(float* d, const uint32_t* a, uint32_t b0, uint32_t b1) {
    asm volatile(
        "mma.sync.aligned.m16n8k16.row.col.f32.f16.f16.f32 "
        "{%0,%1,%2,%3}, {%4,%5,%6,%7}, {%8,%9}, {%0,%1,%2,%3};"
        : "+f"(d[0]), "+f"(d[1]), "+f"(d[2]), "+f"(d[3])
        : "r"(a[0]), "r"(a[1]), "r"(a[2]), "r"(a[3]), "r"(b0), "r"(b1));
}

// ---------------------------------------------------------------------------
// Pre-split half GEMM: C[m][n] = sum_k A[m][k]*B[n][k], inputs are fp16 h/m planes.
// BM=BN=128, BK=32, 256 threads, 8 warps (2m x 4n). 3-stage cp.async.
// PLANES=2: acc += Ah*Bh + Ah*Bm + Am*Bh.  PLANES=1: acc += Ah*Bh.
// OUTSPLIT=1: write Ch/Cm half planes (h=rn(v), m=rn(v-h)); else float C.
// Smem stage: [Ah(8K)][Am(8K)][Bh(8K)][Bm(8K)] (P2) / [Ah][Bh] (P1),
// rows 64B, 16B chunks swizzled by (row + row>>2)&3.
// ---------------------------------------------------------------------------
#define PLANE_B 8192u

template <int PLANES, int OUTSPLIT>
__global__ __launch_bounds__(256) void gemm_h(
    const __half* __restrict__ Ah, const __half* __restrict__ Am,
    const __half* __restrict__ Bh, const __half* __restrict__ Bm,
    float* __restrict__ Cf, __half* __restrict__ Ch, __half* __restrict__ Cm,
    int K, int lda, int ldb, int ldc,
    size_t sA, size_t sB, size_t sC, float c_scale)
{
    extern __shared__ char smc[];
    const uint32_t sbase = smem_u32(smc);
    constexpr uint32_t STAGE_B = PLANES * 2 * PLANE_B;

    const int tid = threadIdx.x;
    const int wid = tid >> 5;
    const int lane = tid & 31;
    const int warp_m = (wid & 1) * 64;
    const int warp_n = (wid >> 1) * 32;

    Ah += (size_t)blockIdx.z * sA;  Am += (size_t)blockIdx.z * sA;
    Bh += (size_t)blockIdx.z * sB;  Bm += (size_t)blockIdx.z * sB;
    const int bm = blockIdx.y * 128;
    const int bn = blockIdx.x * 128;

    // loader: thread -> (row, 2 chunks of 16B)
    const int lrow = tid >> 1;
    const int lc0 = (tid & 1) * 2;
    const int lswz = (lrow + (lrow >> 2)) & 3;
    const __half* Asrc  = Ah + (size_t)(bm + lrow) * lda;
    const __half* Amsrc = Am + (size_t)(bm + lrow) * lda;
    const __half* Bsrc  = Bh + (size_t)(bn + lrow) * ldb;
    const __half* Bmsrc = Bm + (size_t)(bn + lrow) * ldb;

    const int nk = K / 32;

    auto load_stage = [&](int kt, int s) {
        const uint32_t dst = sbase + s * STAGE_B + lrow * 64;
        #pragma unroll
        for (int c = 0; c < 2; c++) {
            const int ch = lc0 + c;
            const uint32_t d = dst + (uint32_t)((ch ^ lswz) << 4);
            const int off = kt * 32 + ch * 8;
            cp16(d, Asrc + off);
            if (PLANES == 2) cp16(d + PLANE_B, Amsrc + off);
            cp16(d + PLANES * PLANE_B, Bsrc + off);
            if (PLANES == 2) cp16(d + 3 * PLANE_B, Bmsrc + off);
        }
        cp_commit();
    };

    load_stage(0, 0);
    load_stage(1, 1);

    float acc[4][4][4];
    #pragma unroll
    for (int i = 0; i < 4; i++)
        #pragma unroll
        for (int j = 0; j < 4; j++)
            #pragma unroll
            for (int t = 0; t < 4; t++)
                acc[i][j][t] = 0.0f;

    // ldmatrix lane addressing
    const int l15 = lane & 15;
    const int hi = lane >> 4;
    const int fswz = (l15 + (l15 >> 2)) & 3;
    const uint32_t kc0 = (uint32_t)((hi ^ fswz) << 4);
    const uint32_t aB0 = sbase + (warp_m + l15) * 64;
    const uint32_t bB0 = sbase + PLANES * PLANE_B + (warp_n + l15) * 64;

    for (int kt = 0; kt < nk; kt++) {
        cp_wait<1>();
        __syncthreads();
        if (kt + 2 < nk) load_stage(kt + 2, (kt + 2) % 3);

        const uint32_t so = (uint32_t)(kt % 3) * STAGE_B;
        const uint32_t sa = aB0 + so;
        const uint32_t sb = bB0 + so;

        #pragma unroll
        for (int kk = 0; kk < 2; kk++) {
            const uint32_t ko = kc0 ^ (kk << 5);
            uint32_t b0[4], b1[4], d0[4], d1[4];
            ldm4(b0, sb + ko);
            ldm4(b1, sb + 1024 + ko);
            if (PLANES == 2) {
                ldm4(d0, sb + PLANE_B + ko);
                ldm4(d1, sb + PLANE_B + 1024 + ko);
            }
            #pragma unroll
            for (int i = 0; i < 4; i++) {
                uint32_t a[4];
                ldm4(a, sa + i * 1024 + ko);
                mma16(acc[i][0], a, b0[0], b0[2]);
                mma16(acc[i][1], a, b0[1], b0[3]);
                mma16(acc[i][2], a, b1[0], b1[2]);
                mma16(acc[i][3], a, b1[1], b1[3]);
                if (PLANES == 2) {
                    uint32_t am[4];
                    ldm4(am, sa + PLANE_B + i * 1024 + ko);
                    mma16(acc[i][0], a, d0[0], d0[2]);
                    mma16(acc[i][1], a, d0[1], d0[3]);
                    mma16(acc[i][2], a, d1[0], d1[2]);
                    mma16(acc[i][3], a, d1[1], d1[3]);
                    mma16(acc[i][0], am, b0[0], b0[2]);
                    mma16(acc[i][1], am, b0[1], b0[3]);
                    mma16(acc[i][2], am, b1[0], b1[2]);
                    mma16(acc[i][3], am, b1[1], b1[3]);
                }
            }
        }
        __syncthreads();
    }

    // epilogue
    const int fr = lane >> 2;
    const int fc = lane & 3;
    #pragma unroll
    for (int i = 0; i < 4; i++) {
        const int row0 = bm + warp_m + i * 16 + fr;
        #pragma unroll
        for (int j = 0; j < 4; j++) {
            const int col = bn + warp_n + j * 8 + fc * 2;
            #pragma unroll
            for (int half_r = 0; half_r < 2; half_r++) {
                const size_t idx = (size_t)(row0 + half_r * 8) * ldc + col;
                const float v0 = acc[i][j][half_r * 2 + 0] * c_scale;
                const float v1 = acc[i][j][half_r * 2 + 1] * c_scale;
                if (OUTSPLIT) {
                    __half2 h = __float22half2_rn(make_float2(v0, v1));
                    float2 hf = __half22float2(h);
                    __half2 mm = __float22half2_rn(make_float2(v0 - hf.x, v1 - hf.y));
                    *(__half2*)((__half*)Ch + (size_t)blockIdx.z * sC + idx) = h;
                    *(__half2*)((__half*)Cm + (size_t)blockIdx.z * sC + idx) = mm;
                } else {
                    *(float2*)(Cf + (size_t)blockIdx.z * sC + idx) = make_float2(v0, v1);
                }
            }
        }
    }
}

// ---------------------------------------------------------------------------
// Elementwise split: h = rn(v*scale), m = rn(v*scale - h).  m may be null.
// ---------------------------------------------------------------------------
__global__ __launch_bounds__(256) void split_f2h(
    const float* __restrict__ src, __half* __restrict__ h, __half* __restrict__ m,
    float scale, size_t n)
{
    const size_t i = ((size_t)blockIdx.x * blockDim.x + threadIdx.x) * 4;
    if (i >= n) return;
    float4 v = *(const float4*)(src + i);
    v.x *= scale; v.y *= scale; v.z *= scale; v.w *= scale;
    __half2 h01 = __float22half2_rn(make_float2(v.x, v.y));
    __half2 h23 = __float22half2_rn(make_float2(v.z, v.w));
    *(__half2*)(h + i) = h01;
    *(__half2*)(h + i + 2) = h23;
    if (m) {
        float2 f01 = __half22float2(h01), f23 = __half22float2(h23);
        *(__half2*)(m + i) = __float22half2_rn(make_float2(v.x - f01.x, v.y - f01.y));
        *(__half2*)(m + i + 2) = __float22half2_rn(make_float2(v.z - f23.x, v.w - f23.y));
    }
}

// ---------------------------------------------------------------------------
// Transpose + split: in[z][R][Cc] float -> oh/om[z][Cc][R] half (om optional)
// ---------------------------------------------------------------------------
__global__ __launch_bounds__(256) void trans_split(
    const float* __restrict__ in, __half* __restrict__ oh, __half* __restrict__ om,
    int R, int Cc)
{
    __shared__ float t[32][33];
    const int bx = blockIdx.x * 32;
    const int by = blockIdx.y * 32;
    const float* ib = in + (size_t)blockIdx.z * R * Cc;
    __half* ob = oh + (size_t)blockIdx.z * R * Cc;
    __half* ob2 = om ? om + (size_t)blockIdx.z * R * Cc : (__half*)0;
    const int x = threadIdx.x, y = threadIdx.y;  // 32 x 8
    #pragma unroll
    for (int i = 0; i < 32; i += 8)
        t[y + i][x] = ib[(size_t)(by + y + i) * Cc + bx + x];
    __syncthreads();
    #pragma unroll
    for (int i = 0; i < 32; i += 8) {
        const float v = t[x][y + i];
        const size_t idx = (size_t)(bx + y + i) * R + by + x;
        __half hv = __float2half_rn(v);
        ob[idx] = hv;
        if (om) ob2[idx] = __float2half_rn(v - __half2float(hv));
    }
}

// ---------------------------------------------------------------------------
// In-place row softmax, row length 1024
// ---------------------------------------------------------------------------
__global__ __launch_bounds__(256) void softmax1024(float* __restrict__ e)
{
    const size_t row = blockIdx.x;
    float* p = e + row * (size_t)HWD;
    const int t = threadIdx.x;

    float v[4];
    float mx = -1e30f;
    #pragma unroll
    for (int i = 0; i < 4; i++) {
        v[i] = p[t + 256 * i];
        mx = fmaxf(mx, v[i]);
    }
    __shared__ float redm[8];
    __shared__ float reds[8];
    #pragma unroll
    for (int o = 16; o > 0; o >>= 1)
        mx = fmaxf(mx, __shfl_xor_sync(0xFFFFFFFFu, mx, o));
    if ((t & 31) == 0) redm[t >> 5] = mx;
    __syncthreads();
    float m = redm[0];
    #pragma unroll
    for (int i = 1; i < 8; i++) m = fmaxf(m, redm[i]);

    float sacc = 0.0f;
    #pragma unroll
    for (int i = 0; i < 4; i++) {
        v[i] = __expf(v[i] - m);
        sacc += v[i];
    }
    #pragma unroll
    for (int o = 16; o > 0; o >>= 1)
        sacc += __shfl_xor_sync(0xFFFFFFFFu, sacc, o);
    if ((t & 31) == 0) reds[t >> 5] = sacc;
    __syncthreads();
    float sum = reds[0];
    #pragma unroll
    for (int i = 1; i < 8; i++) sum += reds[i];

    const float inv = 1.0f / sum;
    #pragma unroll
    for (int i = 0; i < 4; i++)
        p[t + 256 * i] = v[i] * inv;
}

// ---------------------------------------------------------------------------
extern "C" void kernel_launch(void* const* d_in, const int* in_sizes, int n_in,
                              void* d_out, int out_size)
{
    const float* node1 = (const float*)d_in[0];  // [B, C, HW]
    const float* node2 = (const float*)d_in[1];  // [B, C, HW]
    const float* Wc    = (const float*)d_in[2];  // [HW, HW]
    float* out = (float*)d_out;                  // [B, C, HW]

    __half *Wh, *Wm, *n1h, *n1m, *n2h, *n2Th, *n2Tm, *xTh, *xTm, *aTh;
    float* e;
    cudaGetSymbolAddress((void**)&Wh,   g_Wh);
    cudaGetSymbolAddress((void**)&Wm,   g_Wm);
    cudaGetSymbolAddress((void**)&n1h,  g_n1h);
    cudaGetSymbolAddress((void**)&n1m,  g_n1m);
    cudaGetSymbolAddress((void**)&n2h,  g_n2h);
    cudaGetSymbolAddress((void**)&n2Th, g_n2Th);
    cudaGetSymbolAddress((void**)&n2Tm, g_n2Tm);
    cudaGetSymbolAddress((void**)&xTh,  g_xTh);
    cudaGetSymbolAddress((void**)&xTm,  g_xTm);
    cudaGetSymbolAddress((void**)&aTh,  g_aTh);
    cudaGetSymbolAddress((void**)&e,    g_e);

    const int SM2 = 3 * 4 * PLANE_B;  // 96KB for PLANES=2
    const int SM1 = 3 * 2 * PLANE_B;  // 48KB for PLANES=1
    cudaFuncSetAttribute(gemm_h<2, 1>, cudaFuncAttributeMaxDynamicSharedMemorySize, SM2);
    cudaFuncSetAttribute(gemm_h<2, 0>, cudaFuncAttributeMaxDynamicSharedMemorySize, SM2);
    cudaFuncSetAttribute(gemm_h<1, 0>, cudaFuncAttributeMaxDynamicSharedMemorySize, SM1);

    // ---- pre-split passes ----
    // Wc scaled by 2^10 (subnormal guard); GEMM1 epilogue scales by 2^-10.
    split_f2h<<<(HWD * HWD) / 1024, 256>>>(Wc, Wh, Wm, 1024.0f, (size_t)HWD * HWD);
    split_f2h<<<(BB * CC * HWD) / 1024, 256>>>(node1, n1h, n1m, 1.0f, (size_t)BB * CC * HWD);
    split_f2h<<<(BB * CC * HWD) / 1024, 256>>>(node2, n2h, (__half*)0, 1.0f, (size_t)BB * CC * HWD);
    trans_split<<<dim3(HWD / 32, CC / 32, BB), dim3(32, 8)>>>(node2, n2Th, n2Tm, CC, HWD);

    // GEMM1: xT[o][m] = sum_h Wc[o][h]*n1[m][h]; M=1024, N=8192, K=1024; split output
    gemm_h<2, 1><<<dim3(8192 / 128, HWD / 128, 1), 256, SM2>>>(
        Wh, Wm, n1h, n1m, (float*)0, xTh, xTm,
        HWD, HWD, HWD, 8192, 0, 0, 0, 1.0f / 1024.0f);

    // GEMM2: e[b][o][h] = sum_c xT[o][b*512+c]*n2T[b][h][c]; M=1024, N=1024, K=512
    gemm_h<2, 0><<<dim3(HWD / 128, HWD / 128, BB), 256, SM2>>>(
        xTh, xTm, n2Th, n2Tm, e, (__half*)0, (__half*)0,
        CC, 8192, CC, HWD,
        (size_t)CC, (size_t)HWD * CC, (size_t)HWD * HWD, 1.0f);

    // softmax over h, in place
    softmax1024<<<BB * HWD, 256>>>(e);

    // aT[b][j][k] = a[b][k][j], h-plane only
    trans_split<<<dim3(HWD / 32, HWD / 32, BB), dim3(32, 8)>>>(e, aTh, (__half*)0, HWD, HWD);

    // GEMM3: out[b][c][j] = sum_k n2[b][c][k]*aT[b][j][k]; M=512, N=1024, K=1024
    gemm_h<1, 0><<<dim3(HWD / 128, CC / 128, BB), 256, SM1>>>(
        n2h, n2h, aTh, aTh, out, (__half*)0, (__half*)0,
        HWD, HWD, HWD, HWD,
        (size_t)CC * HWD, (size_t)HWD * HWD, (size_t)CC * HWD, 1.0f);
}

// round 8
// speedup vs baseline: 1.5094x; 1.0142x over previous
#include <cuda_runtime.h>
#include <cuda_fp16.h>
#include <cstdint>

#define BB 16
#define CC 512
#define HWD 1024

// Device-global scratch
__device__ __half g_Wh [(size_t)HWD * HWD];
__device__ __half g_Wm [(size_t)HWD * HWD];
__device__ __half g_n1h[(size_t)BB * CC * HWD];
__device__ __half g_n1m[(size_t)BB * CC * HWD];
__device__ __half g_n2h[(size_t)BB * CC * HWD];
__device__ __half g_n2s[(size_t)BB * CC * HWD];    // n2h * invS[k]
__device__ __half g_n2Th[(size_t)BB * HWD * CC];
__device__ __half g_n2Tm[(size_t)BB * HWD * CC];
__device__ __half g_xTh[(size_t)HWD * BB * CC];
__device__ __half g_xTm[(size_t)HWD * BB * CC];
__device__ __half g_eh [(size_t)BB * HWD * HWD];   // unnormalized exp(eT - colmax), half
__device__ float  g_eT [(size_t)BB * HWD * HWD];   // eT[b][j][o]
__device__ uint32_t g_cmax[BB * HWD];              // encoded col max (over j) per (b,o)
__device__ float    g_csum[BB * HWD];              // col sum of exp per (b,o)

// ---------------------------------------------------------------------------
__device__ __forceinline__ uint32_t smem_u32(const void* p) {
    uint32_t a;
    asm("{ .reg .u64 t; cvta.to.shared.u64 t, %1; cvt.u32.u64 %0, t; }" : "=r"(a) : "l"(p));
    return a;
}
__device__ __forceinline__ void cp16(uint32_t saddr, const void* g) {
    asm volatile("cp.async.ca.shared.global [%0], [%1], 16;" :: "r"(saddr), "l"(g));
}
__device__ __forceinline__ void cp_commit() { asm volatile("cp.async.commit_group;"); }
template <int N>
__device__ __forceinline__ void cp_wait() {
    asm volatile("cp.async.wait_group %0;" :: "n"(N));
}
__device__ __forceinline__ void ldm4(uint32_t* r, uint32_t addr) {
    asm volatile("ldmatrix.sync.aligned.m8n8.x4.shared.b16 {%0,%1,%2,%3}, [%4];"
                 : "=r"(r[0]), "=r"(r[1]), "=r"(r[2]), "=r"(r[3]) : "r"(addr));
}
__device__ __forceinline__ void mma16(float* d, const uint32_t* a, uint32_t b0, uint32_t b1) {
    asm volatile(
        "mma.sync.aligned.m16n8k16.row.col.f32.f16.f16.f32 "
        "{%0,%1,%2,%3}, {%4,%5,%6,%7}, {%8,%9}, {%0,%1,%2,%3};"
        : "+f"(d[0]), "+f"(d[1]), "+f"(d[2]), "+f"(d[3])
        : "r"(a[0]), "r"(a[1]), "r"(a[2]), "r"(a[3]), "r"(b0), "r"(b1));
}
// order-preserving float<->uint encoding for atomicMax
__device__ __forceinline__ uint32_t enc_f(float f) {
    uint32_t u = __float_as_uint(f);
    return (u & 0x80000000u) ? ~u : (u | 0x80000000u);
}
__device__ __forceinline__ float dec_f(uint32_t e) {
    uint32_t u = (e & 0x80000000u) ? (e ^ 0x80000000u) : ~e;
    return __uint_as_float(u);
}

// ---------------------------------------------------------------------------
// Pre-split half GEMM: C[m][n] = sum_k A[m][k]*B[n][k], fp16 h/m planes.
// BM=BN=128, BK=32, 256 threads, 8 warps (2m x 4n), 3-stage cp.async.
// PLANES=2: Ah*Bh + Ah*Bm + Am*Bh.  PLANES=1: Ah*Bh.
// OUTSPLIT: write Ch/Cm half planes.  COLMAX: also atomicMax per-column (n) max.
// ---------------------------------------------------------------------------
#define PLANE_B 8192u

template <int PLANES, int OUTSPLIT, int COLMAX>
__global__ __launch_bounds__(256, 2) void gemm_h(
    const __half* __restrict__ Ah, const __half* __restrict__ Am,
    const __half* __restrict__ Bh, const __half* __restrict__ Bm,
    float* __restrict__ Cf, __half* __restrict__ Ch, __half* __restrict__ Cm,
    uint32_t* __restrict__ gmax,
    int K, int lda, int ldb, int ldc,
    size_t sA, size_t sB, size_t sC, float c_scale)
{
    extern __shared__ char smc[];
    const uint32_t sbase = smem_u32(smc);
    constexpr uint32_t STAGE_B = PLANES * 2 * PLANE_B;

    const int tid = threadIdx.x;
    const int wid = tid >> 5;
    const int lane = tid & 31;
    const int warp_m = (wid & 1) * 64;
    const int warp_n = (wid >> 1) * 32;

    Ah += (size_t)blockIdx.z * sA;  Am += (size_t)blockIdx.z * sA;
    Bh += (size_t)blockIdx.z * sB;  Bm += (size_t)blockIdx.z * sB;
    const int bm = blockIdx.y * 128;
    const int bn = blockIdx.x * 128;

    const int lrow = tid >> 1;
    const int lc0 = (tid & 1) * 2;
    const int lswz = (lrow + (lrow >> 2)) & 3;
    const __half* Asrc  = Ah + (size_t)(bm + lrow) * lda;
    const __half* Amsrc = Am + (size_t)(bm + lrow) * lda;
    const __half* Bsrc  = Bh + (size_t)(bn + lrow) * ldb;
    const __half* Bmsrc = Bm + (size_t)(bn + lrow) * ldb;

    const int nk = K / 32;

    auto load_stage = [&](int kt, int s) {
        const uint32_t dst = sbase + s * STAGE_B + lrow * 64;
        #pragma unroll
        for (int c = 0; c < 2; c++) {
            const int ch = lc0 + c;
            const uint32_t d = dst + (uint32_t)((ch ^ lswz) << 4);
            const int off = kt * 32 + ch * 8;
            cp16(d, Asrc + off);
            if (PLANES == 2) cp16(d + PLANE_B, Amsrc + off);
            cp16(d + PLANES * PLANE_B, Bsrc + off);
            if (PLANES == 2) cp16(d + 3 * PLANE_B, Bmsrc + off);
        }
        cp_commit();
    };

    load_stage(0, 0);
    load_stage(1, 1);

    float acc[4][4][4];
    #pragma unroll
    for (int i = 0; i < 4; i++)
        #pragma unroll
        for (int j = 0; j < 4; j++)
            #pragma unroll
            for (int t = 0; t < 4; t++)
                acc[i][j][t] = 0.0f;

    const int l15 = lane & 15;
    const int hi = lane >> 4;
    const int fswz = (l15 + (l15 >> 2)) & 3;
    const uint32_t kc0 = (uint32_t)((hi ^ fswz) << 4);
    const uint32_t aB0 = sbase + (warp_m + l15) * 64;
    const uint32_t bB0 = sbase + PLANES * PLANE_B + (warp_n + l15) * 64;

    for (int kt = 0; kt < nk; kt++) {
        cp_wait<1>();
        __syncthreads();
        if (kt + 2 < nk) load_stage(kt + 2, (kt + 2) % 3);

        const uint32_t so = (uint32_t)(kt % 3) * STAGE_B;
        const uint32_t sa = aB0 + so;
        const uint32_t sb = bB0 + so;

        #pragma unroll
        for (int kk = 0; kk < 2; kk++) {
            const uint32_t ko = kc0 ^ (kk << 5);
            uint32_t b0[4], b1[4], d0[4], d1[4];
            ldm4(b0, sb + ko);
            ldm4(b1, sb + 1024 + ko);
            if (PLANES == 2) {
                ldm4(d0, sb + PLANE_B + ko);
                ldm4(d1, sb + PLANE_B + 1024 + ko);
            }
            #pragma unroll
            for (int i = 0; i < 4; i++) {
                uint32_t a[4];
                ldm4(a, sa + i * 1024 + ko);
                mma16(acc[i][0], a, b0[0], b0[2]);
                mma16(acc[i][1], a, b0[1], b0[3]);
                mma16(acc[i][2], a, b1[0], b1[2]);
                mma16(acc[i][3], a, b1[1], b1[3]);
                if (PLANES == 2) {
                    uint32_t am[4];
                    ldm4(am, sa + PLANE_B + i * 1024 + ko);
                    mma16(acc[i][0], a, d0[0], d0[2]);
                    mma16(acc[i][1], a, d0[1], d0[3]);
                    mma16(acc[i][2], a, d1[0], d1[2]);
                    mma16(acc[i][3], a, d1[1], d1[3]);
                    mma16(acc[i][0], am, b0[0], b0[2]);
                    mma16(acc[i][1], am, b0[1], b0[3]);
                    mma16(acc[i][2], am, b1[0], b1[2]);
                    mma16(acc[i][3], am, b1[1], b1[3]);
                }
            }
        }
        __syncthreads();
    }

    // epilogue
    const int fr = lane >> 2;
    const int fc = lane & 3;
    #pragma unroll
    for (int i = 0; i < 4; i++) {
        const int row0 = bm + warp_m + i * 16 + fr;
        #pragma unroll
        for (int j = 0; j < 4; j++) {
            const int col = bn + warp_n + j * 8 + fc * 2;
            #pragma unroll
            for (int half_r = 0; half_r < 2; half_r++) {
                const size_t idx = (size_t)(row0 + half_r * 8) * ldc + col;
                const float v0 = acc[i][j][half_r * 2 + 0] * c_scale;
                const float v1 = acc[i][j][half_r * 2 + 1] * c_scale;
                if (OUTSPLIT) {
                    __half2 h = __float22half2_rn(make_float2(v0, v1));
                    float2 hf = __half22float2(h);
                    __half2 mm = __float22half2_rn(make_float2(v0 - hf.x, v1 - hf.y));
                    *(__half2*)((__half*)Ch + (size_t)blockIdx.z * sC + idx) = h;
                    *(__half2*)((__half*)Cm + (size_t)blockIdx.z * sC + idx) = mm;
                } else {
                    *(float2*)(Cf + (size_t)blockIdx.z * sC + idx) = make_float2(v0, v1);
                }
            }
        }
    }

    if (COLMAX) {
        // per-column (n) max over this tile's 128 rows -> global atomicMax
        uint32_t* smax = (uint32_t*)smc;
        if (tid < 128) smax[tid] = 0u;
        __syncthreads();
        #pragma unroll
        for (int j = 0; j < 4; j++) {
            #pragma unroll
            for (int u = 0; u < 2; u++) {
                float mv = -3.0e38f;
                #pragma unroll
                for (int i = 0; i < 4; i++) {
                    mv = fmaxf(mv, acc[i][j][u]);
                    mv = fmaxf(mv, acc[i][j][2 + u]);
                }
                atomicMax(&smax[warp_n + j * 8 + fc * 2 + u], enc_f(mv));
            }
        }
        __syncthreads();
        if (tid < 128)
            atomicMax(&gmax[blockIdx.z * HWD + bn + tid], smax[tid]);
    }
}

// ---------------------------------------------------------------------------
// init stats: colmax=0 (encoded -inf-safe floor), colsum=0
// ---------------------------------------------------------------------------
__global__ void init_stats(uint32_t* __restrict__ cmax, float* __restrict__ csum)
{
    const int i = blockIdx.x * blockDim.x + threadIdx.x;
    if (i < BB * HWD) { cmax[i] = 0u; csum[i] = 0.0f; }
}

// ---------------------------------------------------------------------------
// Elementwise split: h = rn(v*scale), m = rn(v*scale - h)
// ---------------------------------------------------------------------------
__global__ __launch_bounds__(256) void split_f2h(
    const float* __restrict__ src, __half* __restrict__ h, __half* __restrict__ m,
    float scale, size_t n)
{
    const size_t i = ((size_t)blockIdx.x * blockDim.x + threadIdx.x) * 4;
    if (i >= n) return;
    float4 v = *(const float4*)(src + i);
    v.x *= scale; v.y *= scale; v.z *= scale; v.w *= scale;
    __half2 h01 = __float22half2_rn(make_float2(v.x, v.y));
    __half2 h23 = __float22half2_rn(make_float2(v.z, v.w));
    *(__half2*)(h + i) = h01;
    *(__half2*)(h + i + 2) = h23;
    float2 f01 = __half22float2(h01), f23 = __half22float2(h23);
    *(__half2*)(m + i) = __float22half2_rn(make_float2(v.x - f01.x, v.y - f01.y));
    *(__half2*)(m + i + 2) = __float22half2_rn(make_float2(v.z - f23.x, v.w - f23.y));
}

// ---------------------------------------------------------------------------
// n2 combo pass: read node2[b][c][k] once; write n2h (same layout, half) and
// n2Th/n2Tm (transposed [k][c], split).
// ---------------------------------------------------------------------------
__global__ __launch_bounds__(256) void n2_prep(
    const float* __restrict__ in, __half* __restrict__ oh,
    __half* __restrict__ th, __half* __restrict__ tm)
{
    __shared__ float t[32][33];
    const int bx = blockIdx.x * 32;   // k
    const int by = blockIdx.y * 32;   // c
    const float* ib = in + (size_t)blockIdx.z * CC * HWD;
    __half* hb = oh + (size_t)blockIdx.z * CC * HWD;
    __half* tb = th + (size_t)blockIdx.z * HWD * CC;
    __half* mb = tm + (size_t)blockIdx.z * HWD * CC;
    const int x = threadIdx.x, y = threadIdx.y;  // 32 x 8
    #pragma unroll
    for (int i = 0; i < 32; i += 8) {
        const float v = ib[(size_t)(by + y + i) * HWD + bx + x];
        t[y + i][x] = v;
        hb[(size_t)(by + y + i) * HWD + bx + x] = __float2half_rn(v);
    }
    __syncthreads();
    #pragma unroll
    for (int i = 0; i < 32; i += 8) {
        const float v = t[x][y + i];
        const size_t idx = (size_t)(bx + y + i) * CC + by + x;
        __half hv = __float2half_rn(v);
        tb[idx] = hv;
        mb[idx] = __float2half_rn(v - __half2float(hv));
    }
}

// ---------------------------------------------------------------------------
// exp pass: eh[b][j][k] = half(exp(eT - colmax[b][k])); accumulate colsum.
// CTA: 256 cols x 128 rows.
// ---------------------------------------------------------------------------
__global__ __launch_bounds__(256) void expnorm(
    const float* __restrict__ eT, __half* __restrict__ eh,
    const uint32_t* __restrict__ cmax, float* __restrict__ csum)
{
    const int b = blockIdx.z;
    const int col = blockIdx.x * 256 + threadIdx.x;
    const int row0 = blockIdx.y * 128;
    const float cm = dec_f(cmax[b * HWD + col]);
    const float* src = eT + (size_t)b * HWD * HWD + (size_t)row0 * HWD + col;
    __half* dst = eh + (size_t)b * HWD * HWD + (size_t)row0 * HWD + col;
    float s = 0.0f;
    #pragma unroll 4
    for (int r = 0; r < 128; r++) {
        const float w = __expf(src[(size_t)r * HWD] - cm);
        s += w;
        dst[(size_t)r * HWD] = __float2half_rn(w);
    }
    atomicAdd(&csum[b * HWD + col], s);
}

// ---------------------------------------------------------------------------
// scale pass: n2s[b][c][k] = n2h * (1/colsum[b][k])
// ---------------------------------------------------------------------------
__global__ __launch_bounds__(256) void scale_n2(
    const __half* __restrict__ n2h, __half* __restrict__ n2s,
    const float* __restrict__ csum)
{
    const size_t i = ((size_t)blockIdx.x * blockDim.x + threadIdx.x) * 4;
    if (i >= (size_t)BB * CC * HWD) return;
    const int b = (int)(i / ((size_t)CC * HWD));
    const int k = (int)(i % HWD);
    const float* cs = csum + b * HWD + k;
    __half2 a01 = *(const __half2*)(n2h + i);
    __half2 a23 = *(const __half2*)(n2h + i + 2);
    float2 f01 = __half22float2(a01), f23 = __half22float2(a23);
    const float i0 = 1.0f / cs[0], i1 = 1.0f / cs[1];
    const float i2 = 1.0f / cs[2], i3 = 1.0f / cs[3];
    *(__half2*)(n2s + i) = __float22half2_rn(make_float2(f01.x * i0, f01.y * i1));
    *(__half2*)(n2s + i + 2) = __float22half2_rn(make_float2(f23.x * i2, f23.y * i3));
}

// ---------------------------------------------------------------------------
extern "C" void kernel_launch(void* const* d_in, const int* in_sizes, int n_in,
                              void* d_out, int out_size)
{
    const float* node1 = (const float*)d_in[0];
    const float* node2 = (const float*)d_in[1];
    const float* Wc    = (const float*)d_in[2];
    float* out = (float*)d_out;

    __half *Wh, *Wm, *n1h, *n1m, *n2h, *n2s, *n2Th, *n2Tm, *xTh, *xTm, *eh;
    float *eT, *csum;
    uint32_t* cmax;
    cudaGetSymbolAddress((void**)&Wh,   g_Wh);
    cudaGetSymbolAddress((void**)&Wm,   g_Wm);
    cudaGetSymbolAddress((void**)&n1h,  g_n1h);
    cudaGetSymbolAddress((void**)&n1m,  g_n1m);
    cudaGetSymbolAddress((void**)&n2h,  g_n2h);
    cudaGetSymbolAddress((void**)&n2s,  g_n2s);
    cudaGetSymbolAddress((void**)&n2Th, g_n2Th);
    cudaGetSymbolAddress((void**)&n2Tm, g_n2Tm);
    cudaGetSymbolAddress((void**)&xTh,  g_xTh);
    cudaGetSymbolAddress((void**)&xTm,  g_xTm);
    cudaGetSymbolAddress((void**)&eh,   g_eh);
    cudaGetSymbolAddress((void**)&eT,   g_eT);
    cudaGetSymbolAddress((void**)&cmax, g_cmax);
    cudaGetSymbolAddress((void**)&csum, g_csum);

    const int SM2 = 3 * 4 * PLANE_B;  // 96KB
    const int SM1 = 3 * 2 * PLANE_B;  // 48KB
    cudaFuncSetAttribute((const void*)gemm_h<2, 1, 0>,
                         cudaFuncAttributeMaxDynamicSharedMemorySize, SM2);
    cudaFuncSetAttribute((const void*)gemm_h<2, 0, 1>,
                         cudaFuncAttributeMaxDynamicSharedMemorySize, SM2);
    cudaFuncSetAttribute((const void*)gemm_h<1, 0, 0>,
                         cudaFuncAttributeMaxDynamicSharedMemorySize, SM1);

    init_stats<<<(BB * HWD + 255) / 256, 256>>>(cmax, csum);

    // pre-splits (Wc scaled 2^10 against fp16 subnormals; undone in GEMM1 epilogue)
    split_f2h<<<(HWD * HWD) / 1024, 256>>>(Wc, Wh, Wm, 1024.0f, (size_t)HWD * HWD);
    split_f2h<<<(BB * CC * HWD) / 1024, 256>>>(node1, n1h, n1m, 1.0f, (size_t)BB * CC * HWD);
    n2_prep<<<dim3(HWD / 32, CC / 32, BB), dim3(32, 8)>>>(node2, n2h, n2Th, n2Tm);

    // GEMM1: xT[o][m] = sum_h Wc[o][h]*n1[m][h]; M=1024, N=8192, K=1024; split out
    gemm_h<2, 1, 0><<<dim3(8192 / 128, HWD / 128, 1), 256, SM2>>>(
        Wh, Wm, n1h, n1m, (float*)0, xTh, xTm, (uint32_t*)0,
        HWD, HWD, HWD, 8192, 0, 0, 0, 1.0f / 1024.0f);

    // GEMM2 (swapped): eT[b][j][o] = sum_c n2T[b][j][c]*xT[o][b*512+c]; + colmax
    gemm_h<2, 0, 1><<<dim3(HWD / 128, HWD / 128, BB), 256, SM2>>>(
        n2Th, n2Tm, xTh, xTm, eT, (__half*)0, (__half*)0, cmax,
        CC, CC, 8192, HWD,
        (size_t)HWD * CC, (size_t)CC, (size_t)HWD * HWD, 1.0f);

    // exp + colsum; writes eh (== aT layout [j][k])
    expnorm<<<dim3(HWD / 256, HWD / 128, BB), 256>>>(eT, eh, cmax, csum);

    // fold softmax normalization into n2's contraction columns
    scale_n2<<<(int)(((size_t)BB * CC * HWD) / 1024), 256>>>(n2h, n2s, csum);

    // GEMM3: out[b][c][j] = sum_k n2s[b][c][k]*eh[b][j][k]; M=512, N=1024, K=1024
    gemm_h<1, 0, 0><<<dim3(HWD / 128, CC / 128, BB), 256, SM1>>>(
        n2s, n2s, eh, eh, out, (__half*)0, (__half*)0, (uint32_t*)0,
        HWD, HWD, HWD, HWD,
        (size_t)CC * HWD, (size_t)HWD * HWD, (size_t)CC * HWD, 1.0f);
}